// round 1
// baseline (speedup 1.0000x reference)
#include <cuda_runtime.h>
#include <math.h>

// Problem constants
#define BB   64
#define TT   512
#define DD   1024
#define HH   1024
#define N3H  3072                // 3*H
#define MM   (BB * TT)           // 32768 rows of gi

// ---------------------------------------------------------------------------
// Scratch (device globals; no allocations allowed)
// ---------------------------------------------------------------------------
__device__ float g_gi[(size_t)MM * N3H];   // precomputed input projection [B*T, 3H]
__device__ float g_h[2][BB * HH];          // ping-pong hidden state

// ---------------------------------------------------------------------------
// init: copy h0 into parity-0 buffer
// ---------------------------------------------------------------------------
__global__ void init_h_kernel(const float* __restrict__ h0)
{
    int i = blockIdx.x * blockDim.x + threadIdx.x;
    if (i < BB * HH) g_h[0][i] = h0[i];
}

// ---------------------------------------------------------------------------
// gi GEMM: C[m, n] = sum_k x[m,k] * W_ih[n,k] + b_ih[n]
// 128x128 block tile, BK=8, 256 threads, 8x8 per thread.
// ---------------------------------------------------------------------------
__global__ __launch_bounds__(256) void gi_gemm_kernel(
    const float* __restrict__ A,     // x, [M, K]
    const float* __restrict__ W,     // W_ih, [N, K]
    const float* __restrict__ bias)  // b_ih, [N]
{
    constexpr int K = DD;
    constexpr int N = N3H;

    __shared__ float As[8][132];
    __shared__ float Bs[8][132];

    const int tid = threadIdx.x;
    const int bm  = blockIdx.y * 128;
    const int bn  = blockIdx.x * 128;

    // cooperative load mapping: 1 float4 per thread per operand per K-tile
    const int lr = tid >> 1;            // 0..127
    const int lk = (tid & 1) << 2;      // 0 or 4

    const float* Ap = A + (size_t)(bm + lr) * K + lk;
    const float* Wp = W + (size_t)(bn + lr) * K + lk;

    // compute mapping: 16x16 thread grid, 8x8 outputs each
    const int tr = (tid >> 4) << 3;     // 0..120
    const int tc = (tid & 15) << 3;     // 0..120

    float acc[8][8];
#pragma unroll
    for (int i = 0; i < 8; ++i)
#pragma unroll
        for (int j = 0; j < 8; ++j) acc[i][j] = 0.0f;

    for (int k0 = 0; k0 < K; k0 += 8) {
        float4 av = *(const float4*)(Ap + k0);
        float4 wv = *(const float4*)(Wp + k0);
        As[lk + 0][lr] = av.x; As[lk + 1][lr] = av.y;
        As[lk + 2][lr] = av.z; As[lk + 3][lr] = av.w;
        Bs[lk + 0][lr] = wv.x; Bs[lk + 1][lr] = wv.y;
        Bs[lk + 2][lr] = wv.z; Bs[lk + 3][lr] = wv.w;
        __syncthreads();

#pragma unroll
        for (int kk = 0; kk < 8; ++kk) {
            float ra[8], rb[8];
#pragma unroll
            for (int i = 0; i < 8; ++i) ra[i] = As[kk][tr + i];
#pragma unroll
            for (int j = 0; j < 8; ++j) rb[j] = Bs[kk][tc + j];
#pragma unroll
            for (int i = 0; i < 8; ++i)
#pragma unroll
                for (int j = 0; j < 8; ++j)
                    acc[i][j] = fmaf(ra[i], rb[j], acc[i][j]);
        }
        __syncthreads();
    }

#pragma unroll
    for (int i = 0; i < 8; ++i) {
#pragma unroll
        for (int j = 0; j < 8; ++j) {
            int col = bn + tc + j;
            g_gi[(size_t)(bm + tr + i) * N + col] = acc[i][j] + bias[col];
        }
    }
}

// ---------------------------------------------------------------------------
// One GRU time step.
// Grid: (H/32, B/16) = (32, 4) = 128 blocks, 256 threads.
// Each thread: 1 column j, 2 batches (bp, bp+8), 3 gate accumulators each.
// W_hh rows and masked h staged in SMEM; conflict-free float4 reads.
// ---------------------------------------------------------------------------
__global__ __launch_bounds__(256) void gru_step_kernel(
    const float* __restrict__ Whh,    // [3H, H]
    const float* __restrict__ bhh,    // [3H]
    const int*   __restrict__ dones,  // [B, T]
    float*       __restrict__ out,    // [B, T, H]
    int t, int par)
{
    constexpr int H = HH, T = TT;
    constexpr int Jb = 32, Bbt = 16, BK = 64;

    __shared__ float Hs[Bbt][BK];
    __shared__ float Ws[3 * Jb][BK + 4];

    const float* __restrict__ hin  = g_h[par];
    float*       __restrict__ hout = g_h[par ^ 1];

    const int tid  = threadIdx.x;
    const int jblk = blockIdx.x * Jb;
    const int bblk = blockIdx.y * Bbt;

    const int j  = tid & 31;          // column within tile
    const int bp = tid >> 5;          // 0..7 -> batches bp, bp+8

    float ar0 = 0.f, az0 = 0.f, an0 = 0.f;
    float ar1 = 0.f, az1 = 0.f, an1 = 0.f;

    // loader mapping for Hs
    const int ldb = tid >> 4;               // 0..15
    const int ldk = (tid & 15) << 2;        // 0..60
    const float hmask = 1.0f - (float)dones[(size_t)(bblk + ldb) * T + t];

    for (int k0 = 0; k0 < H; k0 += BK) {
        // load masked h tile [16][64]
        {
            float4 v = *(const float4*)(hin + (size_t)(bblk + ldb) * H + k0 + ldk);
            v.x *= hmask; v.y *= hmask; v.z *= hmask; v.w *= hmask;
            *(float4*)&Hs[ldb][ldk] = v;
        }
        // load W tile: 96 rows x 64 cols, 6 float4 per thread, coalesced
#pragma unroll
        for (int q = 0; q < 6; ++q) {
            int idx = q * 256 + tid;        // 0..1535
            int r   = idx >> 4;             // 0..95
            int kk  = (idx & 15) << 2;
            int g   = r >> 5;               // gate 0..2
            int jj  = r & 31;
            float4 w = *(const float4*)(Whh + (size_t)(g * H + jblk + jj) * H + k0 + kk);
            *(float4*)&Ws[r][kk] = w;
        }
        __syncthreads();

#pragma unroll
        for (int kk = 0; kk < BK; kk += 4) {
            float4 h0v = *(const float4*)&Hs[bp][kk];        // uniform per warp
            float4 h1v = *(const float4*)&Hs[bp + 8][kk];    // uniform per warp
            float4 wr  = *(const float4*)&Ws[j][kk];
            float4 wz  = *(const float4*)&Ws[Jb + j][kk];
            float4 wn  = *(const float4*)&Ws[2 * Jb + j][kk];

            ar0 = fmaf(h0v.x, wr.x, ar0); ar0 = fmaf(h0v.y, wr.y, ar0);
            ar0 = fmaf(h0v.z, wr.z, ar0); ar0 = fmaf(h0v.w, wr.w, ar0);
            az0 = fmaf(h0v.x, wz.x, az0); az0 = fmaf(h0v.y, wz.y, az0);
            az0 = fmaf(h0v.z, wz.z, az0); az0 = fmaf(h0v.w, wz.w, az0);
            an0 = fmaf(h0v.x, wn.x, an0); an0 = fmaf(h0v.y, wn.y, an0);
            an0 = fmaf(h0v.z, wn.z, an0); an0 = fmaf(h0v.w, wn.w, an0);

            ar1 = fmaf(h1v.x, wr.x, ar1); ar1 = fmaf(h1v.y, wr.y, ar1);
            ar1 = fmaf(h1v.z, wr.z, ar1); ar1 = fmaf(h1v.w, wr.w, ar1);
            az1 = fmaf(h1v.x, wz.x, az1); az1 = fmaf(h1v.y, wz.y, az1);
            az1 = fmaf(h1v.z, wz.z, az1); az1 = fmaf(h1v.w, wz.w, az1);
            an1 = fmaf(h1v.x, wn.x, an1); an1 = fmaf(h1v.y, wn.y, an1);
            an1 = fmaf(h1v.z, wn.z, an1); an1 = fmaf(h1v.w, wn.w, an1);
        }
        __syncthreads();
    }

    const int jg = jblk + j;
    const float br = bhh[jg];
    const float bz = bhh[H + jg];
    const float bn = bhh[2 * H + jg];

#pragma unroll
    for (int half = 0; half < 2; ++half) {
        int   b  = bblk + bp + half * 8;
        float gr = half ? ar1 : ar0;
        float gz = half ? az1 : az0;
        float gn = half ? an1 : an0;

        float m  = 1.0f - (float)dones[(size_t)b * T + t];
        float hm = hin[(size_t)b * H + jg] * m;

        const float* gip = g_gi + ((size_t)b * T + t) * N3H;
        float r  = 1.0f / (1.0f + expf(-(gip[jg]         + gr + br)));
        float z  = 1.0f / (1.0f + expf(-(gip[H + jg]     + gz + bz)));
        float n  = tanhf(gip[2 * H + jg] + r * (gn + bn));
        float hn = (1.0f - z) * n + z * hm;

        out[((size_t)b * T + t) * H + jg] = hn;
        hout[(size_t)b * H + jg]          = hn;
    }
}

// ---------------------------------------------------------------------------
// copy final hidden state (parity-0 buffer after 512 steps) to output tail
// ---------------------------------------------------------------------------
__global__ void copy_hlast_kernel(float* __restrict__ dst)
{
    int i = blockIdx.x * blockDim.x + threadIdx.x;
    if (i < BB * HH) dst[i] = g_h[0][i];
}

// ---------------------------------------------------------------------------
// launch
// ---------------------------------------------------------------------------
extern "C" void kernel_launch(void* const* d_in, const int* in_sizes, int n_in,
                              void* d_out, int out_size)
{
    const float* x     = (const float*)d_in[0];  // [B,T,D]
    const float* h0    = (const float*)d_in[1];  // [1,B,H]
    const int*   dones = (const int*)  d_in[2];  // [B,T]
    const float* Wih   = (const float*)d_in[3];  // [3H,D]
    const float* Whh   = (const float*)d_in[4];  // [3H,H]
    const float* bih   = (const float*)d_in[5];  // [3H]
    const float* bhh   = (const float*)d_in[6];  // [3H]

    float* out   = (float*)d_out;                          // outs [B,T,H]
    float* hlast = out + (size_t)BB * TT * HH;             // h_last [1,B,H]

    // hidden-state init
    init_h_kernel<<<(BB * HH + 255) / 256, 256>>>(h0);

    // input projection gi = x @ W_ih^T + b_ih
    {
        dim3 grid(N3H / 128, MM / 128);   // (24, 256)
        gi_gemm_kernel<<<grid, 256>>>(x, Wih, bih);
    }

    // sequential scan
    {
        dim3 grid(HH / 32, BB / 16);      // (32, 4) = 128 blocks
        for (int t = 0; t < TT; ++t) {
            gru_step_kernel<<<grid, 256>>>(Whh, bhh, dones, out, t, t & 1);
        }
    }

    // final hidden state (after 512 steps, parity back to buffer 0)
    copy_hlast_kernel<<<(BB * HH + 255) / 256, 256>>>(hlast);
}

// round 2
// speedup vs baseline: 1.5361x; 1.5361x over previous
#include <cuda_runtime.h>
#include <cuda_bf16.h>
#include <math.h>

#define BB   64
#define TT   512
#define DD   1024
#define HH   1024
#define N3H  3072
#define MM   (BB * TT)     // 32768
#define KP   512           // K/2 packed u32 pairs

// ---------------------------------------------------------------------------
// Scratch (device globals)
// ---------------------------------------------------------------------------
__device__ float    g_gi[(size_t)MM * N3H];        // input projection fp32
__device__ unsigned g_xhi[(size_t)MM * KP];        // x packed bf16x2 (hi)
__device__ unsigned g_xlo[(size_t)MM * KP];        // x packed bf16x2 (lo)
__device__ unsigned g_wihhi[(size_t)N3H * KP];
__device__ unsigned g_wihlo[(size_t)N3H * KP];
__device__ unsigned g_whhhi[(size_t)N3H * KP];
__device__ unsigned g_whhlo[(size_t)N3H * KP];
__device__ unsigned g_hhi[2][BB * KP];             // masked h, ping-pong
__device__ unsigned g_hlo[2][BB * KP];
__device__ float    g_h[BB * HH];                  // unmasked h fp32 (single buffer)

// ---------------------------------------------------------------------------
// helpers
// ---------------------------------------------------------------------------
__device__ __forceinline__ void pack2(float v0, float v1, unsigned& hi, unsigned& lo)
{
    __nv_bfloat16 h0 = __float2bfloat16(v0);
    __nv_bfloat16 h1 = __float2bfloat16(v1);
    float r0 = v0 - __bfloat162float(h0);
    float r1 = v1 - __bfloat162float(h1);
    __nv_bfloat16 l0 = __float2bfloat16(r0);
    __nv_bfloat16 l1 = __float2bfloat16(r1);
    hi = (unsigned)__bfloat16_as_ushort(h0) | ((unsigned)__bfloat16_as_ushort(h1) << 16);
    lo = (unsigned)__bfloat16_as_ushort(l0) | ((unsigned)__bfloat16_as_ushort(l1) << 16);
}

__device__ __forceinline__ void mma_bf16(float* d,
    unsigned a0, unsigned a1, unsigned a2, unsigned a3,
    unsigned b0, unsigned b1)
{
    asm volatile(
        "mma.sync.aligned.m16n8k16.row.col.f32.bf16.bf16.f32 "
        "{%0,%1,%2,%3},{%4,%5,%6,%7},{%8,%9},{%0,%1,%2,%3};\n"
        : "+f"(d[0]), "+f"(d[1]), "+f"(d[2]), "+f"(d[3])
        : "r"(a0), "r"(a1), "r"(a2), "r"(a3), "r"(b0), "r"(b1));
}

__device__ __forceinline__ float sigf(float x) { return 1.0f / (1.0f + expf(-x)); }

// ---------------------------------------------------------------------------
// pack kernels
// ---------------------------------------------------------------------------
__global__ void pack_x_kernel(const float* __restrict__ src)
{
    size_t i = (size_t)blockIdx.x * 256 + threadIdx.x;
    if (i >= (size_t)MM * KP) return;
    float2 v = ((const float2*)src)[i];
    unsigned h, l; pack2(v.x, v.y, h, l);
    g_xhi[i] = h; g_xlo[i] = l;
}

__global__ void pack_w_kernel(const float* __restrict__ src, int which)
{
    size_t i = (size_t)blockIdx.x * 256 + threadIdx.x;
    if (i >= (size_t)N3H * KP) return;
    float2 v = ((const float2*)src)[i];
    unsigned h, l; pack2(v.x, v.y, h, l);
    if (which == 0) { g_wihhi[i] = h; g_wihlo[i] = l; }
    else            { g_whhhi[i] = h; g_whhlo[i] = l; }
}

__global__ void init_h_kernel(const float* __restrict__ h0, const int* __restrict__ dones)
{
    int i = blockIdx.x * 256 + threadIdx.x;   // over BB*KP pairs
    if (i >= BB * KP) return;
    int b = i >> 9, p = i & 511;
    float v0 = h0[b * HH + 2 * p];
    float v1 = h0[b * HH + 2 * p + 1];
    g_h[b * HH + 2 * p]     = v0;
    g_h[b * HH + 2 * p + 1] = v1;
    float m = 1.0f - (float)dones[b * TT + 0];
    unsigned h, l; pack2(v0 * m, v1 * m, h, l);
    g_hhi[0][i] = h; g_hlo[0][i] = l;
}

__global__ void copy_hlast_kernel(float* __restrict__ dst)
{
    int i = blockIdx.x * 256 + threadIdx.x;
    if (i < BB * HH) dst[i] = g_h[i];
}

// ---------------------------------------------------------------------------
// gi GEMM: g_gi[m][n] = sum_k x[m][k]*W_ih[n][k] + b_ih[n]   (bf16 hi/lo, 3 mma passes)
// block tile 128x128, 512 thr, 16 warps of 32x32.
// ---------------------------------------------------------------------------
__global__ __launch_bounds__(512) void gi_gemm_kernel(const float* __restrict__ bias)
{
    __shared__ unsigned sAh[128][20], sAl[128][20], sBh[128][20], sBl[128][20];

    const int tid  = threadIdx.x;
    const int lane = tid & 31;
    const int wid  = tid >> 5;
    const int n0   = blockIdx.x * 128;
    const int m0   = blockIdx.y * 128;
    const int mw   = (wid & 3) * 32;
    const int nw   = (wid >> 2) * 32;
    const int g    = lane >> 2;
    const int t4   = lane & 3;

    float Da[8][4], Db[8][4];
#pragma unroll
    for (int i = 0; i < 8; ++i)
#pragma unroll
        for (int j = 0; j < 4; ++j) { Da[i][j] = 0.f; Db[i][j] = 0.f; }

    const int lrow = tid >> 2;          // 0..127
    const int lq   = (tid & 3) * 4;     // 0,4,8,12

    for (int c = 0; c < 32; ++c) {
        size_t abase = (size_t)(m0 + lrow) * KP + c * 16 + lq;
        size_t bbase = (size_t)(n0 + lrow) * KP + c * 16 + lq;
        *(uint4*)&sAh[lrow][lq] = *(const uint4*)&g_xhi[abase];
        *(uint4*)&sAl[lrow][lq] = *(const uint4*)&g_xlo[abase];
        *(uint4*)&sBh[lrow][lq] = *(const uint4*)&g_wihhi[bbase];
        *(uint4*)&sBl[lrow][lq] = *(const uint4*)&g_wihlo[bbase];
        __syncthreads();

#pragma unroll
        for (int kt = 0; kt < 2; ++kt) {
            const int o = kt * 8;
            unsigned ahi[2][4], alo[2][4], bhi[4][2];
#pragma unroll
            for (int mt = 0; mt < 2; ++mt) {
                int r = mw + mt * 16 + g;
                ahi[mt][0] = sAh[r][o + t4];     ahi[mt][1] = sAh[r + 8][o + t4];
                ahi[mt][2] = sAh[r][o + 4 + t4]; ahi[mt][3] = sAh[r + 8][o + 4 + t4];
                alo[mt][0] = sAl[r][o + t4];     alo[mt][1] = sAl[r + 8][o + t4];
                alo[mt][2] = sAl[r][o + 4 + t4]; alo[mt][3] = sAl[r + 8][o + 4 + t4];
            }
#pragma unroll
            for (int nt = 0; nt < 4; ++nt) {
                int rn = nw + nt * 8 + g;
                bhi[nt][0] = sBh[rn][o + t4];
                bhi[nt][1] = sBh[rn][o + 4 + t4];
            }
#pragma unroll
            for (int nt = 0; nt < 4; ++nt)
#pragma unroll
                for (int mt = 0; mt < 2; ++mt)
                    mma_bf16(Da[nt * 2 + mt], ahi[mt][0], ahi[mt][1], ahi[mt][2], ahi[mt][3],
                             bhi[nt][0], bhi[nt][1]);
#pragma unroll
            for (int nt = 0; nt < 4; ++nt)
#pragma unroll
                for (int mt = 0; mt < 2; ++mt)
                    mma_bf16(Db[nt * 2 + mt], alo[mt][0], alo[mt][1], alo[mt][2], alo[mt][3],
                             bhi[nt][0], bhi[nt][1]);
#pragma unroll
            for (int nt = 0; nt < 4; ++nt) {
                int rn = nw + nt * 8 + g;
                unsigned bl0 = sBl[rn][o + t4];
                unsigned bl1 = sBl[rn][o + 4 + t4];
#pragma unroll
                for (int mt = 0; mt < 2; ++mt)
                    mma_bf16(Db[nt * 2 + mt], ahi[mt][0], ahi[mt][1], ahi[mt][2], ahi[mt][3],
                             bl0, bl1);
            }
        }
        __syncthreads();
    }

#pragma unroll
    for (int nt = 0; nt < 4; ++nt) {
        int col = n0 + nw + nt * 8 + 2 * t4;
        float bs0 = bias[col], bs1 = bias[col + 1];
#pragma unroll
        for (int mt = 0; mt < 2; ++mt) {
            int idx = nt * 2 + mt;
            int row = m0 + mw + mt * 16 + g;
            g_gi[(size_t)row * N3H + col]           = Da[idx][0] + Db[idx][0] + bs0;
            g_gi[(size_t)row * N3H + col + 1]       = Da[idx][1] + Db[idx][1] + bs1;
            g_gi[(size_t)(row + 8) * N3H + col]     = Da[idx][2] + Db[idx][2] + bs0;
            g_gi[(size_t)(row + 8) * N3H + col + 1] = Da[idx][3] + Db[idx][3] + bs1;
        }
    }
}

// ---------------------------------------------------------------------------
// GRU step: gh = (masked h) @ W_hh^T ; fused gates + output + next-step pack.
// 128 blocks (8 h-cols x 3 gates each), 256 thr; warp = (mtile 0..3, khalf 0..1).
// Dynamic SMEM layout:
//   sA u32 [2][2][64][36]  (khalf, hi/lo, batch, 36-stride)  = 18432 u32
//   sW u32 [2][2][24][36]                                     =  6912 u32
//   red f32 [4][32][12]                                       =  1536 f32
// ---------------------------------------------------------------------------
#define SA(h,a,r,c) sA[((((h)*2+(a))*64+(r))*36)+(c)]
#define SW(h,a,r,c) sW[((((h)*2+(a))*24+(r))*36)+(c)]

__global__ __launch_bounds__(256) void gru_step_kernel(
    const int*   __restrict__ dones,
    const float* __restrict__ bhh,
    float*       __restrict__ out,
    int t, int par)
{
    extern __shared__ unsigned smem[];
    unsigned* sA  = smem;
    unsigned* sW  = smem + 2 * 2 * 64 * 36;
    float*    red = (float*)(smem + 2 * 2 * 64 * 36 + 2 * 2 * 24 * 36);

    const int tid  = threadIdx.x;
    const int lane = tid & 31;
    const int wid  = tid >> 5;
    const int mt   = wid & 3;
    const int kh   = wid >> 2;
    const int g    = lane >> 2;
    const int t4   = lane & 3;
    const int j0   = blockIdx.x * 8;

    const unsigned* __restrict__ hhi = g_hhi[par];
    const unsigned* __restrict__ hlo = g_hlo[par];

    float Dhh[3][4], Dhl[3][4], Dlh[3][4];
#pragma unroll
    for (int gg = 0; gg < 3; ++gg)
#pragma unroll
        for (int i = 0; i < 4; ++i) { Dhh[gg][i] = 0.f; Dhl[gg][i] = 0.f; Dlh[gg][i] = 0.f; }

    const int arow = tid >> 2;        // 0..63
    const int aq   = (tid & 3) * 4;   // 0,4,8,12

    for (int c = 0; c < 8; ++c) {
        // stage A (h) for both k-halves, hi and lo
#pragma unroll
        for (int h2 = 0; h2 < 2; ++h2) {
            size_t gb = (size_t)arow * KP + h2 * 256 + c * 32 + aq;
            uint4 v0 = *(const uint4*)&hhi[gb];
            uint4 v1 = *(const uint4*)&hhi[gb + 16];
            *(uint4*)&SA(h2, 0, arow, aq)      = v0;
            *(uint4*)&SA(h2, 0, arow, aq + 16) = v1;
            uint4 w0 = *(const uint4*)&hlo[gb];
            uint4 w1 = *(const uint4*)&hlo[gb + 16];
            *(uint4*)&SA(h2, 1, arow, aq)      = w0;
            *(uint4*)&SA(h2, 1, arow, aq + 16) = w1;
        }
        // stage W: 24 rows x 32 u32 x (2 halves)(2 arr) = 768 uint4; 3 per thread
#pragma unroll
        for (int q = 0; q < 3; ++q) {
            int i    = q * 256 + tid;       // 0..767
            int sel  = i / 192;             // (h2, arr)
            int rem  = i % 192;
            int row  = rem >> 3;            // 0..23
            int u4   = rem & 7;
            int h2   = sel >> 1;
            int arr  = sel & 1;
            int wr   = (row >> 3) * HH + j0 + (row & 7);   // gate*1024 + j
            const unsigned* src = (arr ? g_whhlo : g_whhhi);
            uint4 v = *(const uint4*)&src[(size_t)wr * KP + h2 * 256 + c * 32 + u4 * 4];
            *(uint4*)&SW(h2, arr, row, u4 * 4) = v;
        }
        __syncthreads();

#pragma unroll
        for (int kt = 0; kt < 4; ++kt) {
            const int o  = kt * 8;
            const int ar = mt * 16 + g;
            unsigned ahi0 = SA(kh, 0, ar,     o + t4);
            unsigned ahi1 = SA(kh, 0, ar + 8, o + t4);
            unsigned ahi2 = SA(kh, 0, ar,     o + 4 + t4);
            unsigned ahi3 = SA(kh, 0, ar + 8, o + 4 + t4);
            unsigned alo0 = SA(kh, 1, ar,     o + t4);
            unsigned alo1 = SA(kh, 1, ar + 8, o + t4);
            unsigned alo2 = SA(kh, 1, ar,     o + 4 + t4);
            unsigned alo3 = SA(kh, 1, ar + 8, o + 4 + t4);
            unsigned bh[3][2], bl[3][2];
#pragma unroll
            for (int gg = 0; gg < 3; ++gg) {
                int wr = gg * 8 + g;
                bh[gg][0] = SW(kh, 0, wr, o + t4);
                bh[gg][1] = SW(kh, 0, wr, o + 4 + t4);
                bl[gg][0] = SW(kh, 1, wr, o + t4);
                bl[gg][1] = SW(kh, 1, wr, o + 4 + t4);
            }
#pragma unroll
            for (int gg = 0; gg < 3; ++gg)
                mma_bf16(Dhh[gg], ahi0, ahi1, ahi2, ahi3, bh[gg][0], bh[gg][1]);
#pragma unroll
            for (int gg = 0; gg < 3; ++gg)
                mma_bf16(Dhl[gg], ahi0, ahi1, ahi2, ahi3, bl[gg][0], bl[gg][1]);
#pragma unroll
            for (int gg = 0; gg < 3; ++gg)
                mma_bf16(Dlh[gg], alo0, alo1, alo2, alo3, bh[gg][0], bh[gg][1]);
        }
        __syncthreads();
    }

    // combine passes, reduce across k-halves
    float Dg[3][4];
#pragma unroll
    for (int gg = 0; gg < 3; ++gg)
#pragma unroll
        for (int i = 0; i < 4; ++i)
            Dg[gg][i] = Dhh[gg][i] + Dhl[gg][i] + Dlh[gg][i];

    if (kh == 1) {
#pragma unroll
        for (int gg = 0; gg < 3; ++gg)
#pragma unroll
            for (int i = 0; i < 4; ++i)
                red[(mt * 32 + lane) * 12 + gg * 4 + i] = Dg[gg][i];
    }
    __syncthreads();
    if (kh == 1) return;

#pragma unroll
    for (int gg = 0; gg < 3; ++gg)
#pragma unroll
        for (int i = 0; i < 4; ++i)
            Dg[gg][i] += red[(mt * 32 + lane) * 12 + gg * 4 + i];

    // epilogue: gates + output + next-step packed h
    const int jc  = j0 + 2 * t4;
    const float br0 = bhh[jc],          br1 = bhh[jc + 1];
    const float bz0 = bhh[HH + jc],     bz1 = bhh[HH + jc + 1];
    const float bn0 = bhh[2 * HH + jc], bn1 = bhh[2 * HH + jc + 1];

#pragma unroll
    for (int rs = 0; rs < 2; ++rs) {
        const int b  = mt * 16 + g + rs * 8;
        const int i0 = rs * 2;
        const float m = 1.0f - (float)dones[b * TT + t];
        const size_t gib = ((size_t)b * TT + t) * N3H;

        float h0v = g_h[b * HH + jc]     * m;
        float h1v = g_h[b * HH + jc + 1] * m;

        float r0 = sigf(g_gi[gib + jc]     + Dg[0][i0]     + br0);
        float r1 = sigf(g_gi[gib + jc + 1] + Dg[0][i0 + 1] + br1);
        float z0 = sigf(g_gi[gib + HH + jc]     + Dg[1][i0]     + bz0);
        float z1 = sigf(g_gi[gib + HH + jc + 1] + Dg[1][i0 + 1] + bz1);
        float n0 = tanhf(g_gi[gib + 2 * HH + jc]     + r0 * (Dg[2][i0]     + bn0));
        float n1 = tanhf(g_gi[gib + 2 * HH + jc + 1] + r1 * (Dg[2][i0 + 1] + bn1));

        float hn0 = (1.0f - z0) * n0 + z0 * h0v;
        float hn1 = (1.0f - z1) * n1 + z1 * h1v;

        out[((size_t)b * TT + t) * HH + jc]     = hn0;
        out[((size_t)b * TT + t) * HH + jc + 1] = hn1;
        g_h[b * HH + jc]     = hn0;
        g_h[b * HH + jc + 1] = hn1;

        float nm = (t + 1 < TT) ? (1.0f - (float)dones[b * TT + t + 1]) : 1.0f;
        unsigned ph, pl;
        pack2(hn0 * nm, hn1 * nm, ph, pl);
        g_hhi[par ^ 1][b * KP + (jc >> 1)] = ph;
        g_hlo[par ^ 1][b * KP + (jc >> 1)] = pl;
    }
}

// ---------------------------------------------------------------------------
// launch
// ---------------------------------------------------------------------------
extern "C" void kernel_launch(void* const* d_in, const int* in_sizes, int n_in,
                              void* d_out, int out_size)
{
    const float* x     = (const float*)d_in[0];
    const float* h0    = (const float*)d_in[1];
    const int*   dones = (const int*)  d_in[2];
    const float* Wih   = (const float*)d_in[3];
    const float* Whh   = (const float*)d_in[4];
    const float* bih   = (const float*)d_in[5];
    const float* bhh   = (const float*)d_in[6];

    float* out   = (float*)d_out;
    float* hlast = out + (size_t)BB * TT * HH;

    const int STEP_SMEM = (2 * 2 * 64 * 36 + 2 * 2 * 24 * 36) * 4 + 4 * 32 * 12 * 4; // 107520
    cudaFuncSetAttribute(gru_step_kernel, cudaFuncAttributeMaxDynamicSharedMemorySize, STEP_SMEM);

    // pack inputs to bf16 hi/lo pairs
    pack_x_kernel<<<(MM * KP + 255) / 256, 256>>>(x);
    pack_w_kernel<<<(N3H * KP + 255) / 256, 256>>>(Wih, 0);
    pack_w_kernel<<<(N3H * KP + 255) / 256, 256>>>(Whh, 1);
    init_h_kernel<<<(BB * KP + 255) / 256, 256>>>(h0, dones);

    // gi = x @ W_ih^T + b_ih
    {
        dim3 grid(N3H / 128, MM / 128);   // (24, 256)
        gi_gemm_kernel<<<grid, 512>>>(bih);
    }

    // sequential scan
    for (int t = 0; t < TT; ++t) {
        gru_step_kernel<<<128, 256, STEP_SMEM>>>(dones, bhh, out, t, t & 1);
    }

    copy_hlast_kernel<<<(BB * HH + 255) / 256, 256>>>(hlast);
}

// round 3
// speedup vs baseline: 2.5593x; 1.6661x over previous
#include <cuda_runtime.h>
#include <cuda_bf16.h>
#include <math.h>

#define BB   64
#define TT   512
#define DD   1024
#define HH   1024
#define N3H  3072
#define MM   (BB * TT)     // 32768
#define KP   512           // K/2 packed u32 pairs

// ---------------------------------------------------------------------------
// Scratch (device globals)
// ---------------------------------------------------------------------------
__device__ float    g_gi[(size_t)MM * N3H];
__device__ unsigned g_xhi[(size_t)MM * KP];
__device__ unsigned g_xlo[(size_t)MM * KP];
__device__ unsigned g_wihhi[(size_t)N3H * KP];
__device__ unsigned g_wihlo[(size_t)N3H * KP];
__device__ unsigned g_whhhi[(size_t)N3H * KP];
__device__ unsigned g_whhlo[(size_t)N3H * KP];
__device__ unsigned g_hhi[2][BB * KP];
__device__ unsigned g_hlo[2][BB * KP];
__device__ float    g_h[BB * HH];
__device__ unsigned g_bar;                 // software grid barrier counter

// ---------------------------------------------------------------------------
// helpers
// ---------------------------------------------------------------------------
__device__ __forceinline__ void pack2(float v0, float v1, unsigned& hi, unsigned& lo)
{
    __nv_bfloat16 h0 = __float2bfloat16(v0);
    __nv_bfloat16 h1 = __float2bfloat16(v1);
    float r0 = v0 - __bfloat162float(h0);
    float r1 = v1 - __bfloat162float(h1);
    __nv_bfloat16 l0 = __float2bfloat16(r0);
    __nv_bfloat16 l1 = __float2bfloat16(r1);
    hi = (unsigned)__bfloat16_as_ushort(h0) | ((unsigned)__bfloat16_as_ushort(h1) << 16);
    lo = (unsigned)__bfloat16_as_ushort(l0) | ((unsigned)__bfloat16_as_ushort(l1) << 16);
}

__device__ __forceinline__ void mma_bf16(float* d,
    unsigned a0, unsigned a1, unsigned a2, unsigned a3,
    unsigned b0, unsigned b1)
{
    asm volatile(
        "mma.sync.aligned.m16n8k16.row.col.f32.bf16.bf16.f32 "
        "{%0,%1,%2,%3},{%4,%5,%6,%7},{%8,%9},{%0,%1,%2,%3};\n"
        : "+f"(d[0]), "+f"(d[1]), "+f"(d[2]), "+f"(d[3])
        : "r"(a0), "r"(a1), "r"(a2), "r"(a3), "r"(b0), "r"(b1));
}

__device__ __forceinline__ float sigf(float x) { return 1.0f / (1.0f + expf(-x)); }

__device__ __forceinline__ unsigned ld_acquire_u32(unsigned* p)
{
    unsigned v;
    asm volatile("ld.acquire.gpu.u32 %0, [%1];" : "=r"(v) : "l"(p) : "memory");
    return v;
}

// ---------------------------------------------------------------------------
// pack kernels
// ---------------------------------------------------------------------------
__global__ void pack_x_kernel(const float* __restrict__ src)
{
    size_t i = (size_t)blockIdx.x * 256 + threadIdx.x;
    if (i >= (size_t)MM * KP) return;
    float2 v = ((const float2*)src)[i];
    unsigned h, l; pack2(v.x, v.y, h, l);
    g_xhi[i] = h; g_xlo[i] = l;
}

__global__ void pack_w_kernel(const float* __restrict__ src, int which)
{
    size_t i = (size_t)blockIdx.x * 256 + threadIdx.x;
    if (i >= (size_t)N3H * KP) return;
    float2 v = ((const float2*)src)[i];
    unsigned h, l; pack2(v.x, v.y, h, l);
    if (which == 0) { g_wihhi[i] = h; g_wihlo[i] = l; }
    else            { g_whhhi[i] = h; g_whhlo[i] = l; }
}

__global__ void init_h_kernel(const float* __restrict__ h0, const int* __restrict__ dones)
{
    int i = blockIdx.x * 256 + threadIdx.x;
    if (i == 0) g_bar = 0;                    // reset barrier each launch/replay
    if (i >= BB * KP) return;
    int b = i >> 9, p = i & 511;
    float v0 = h0[b * HH + 2 * p];
    float v1 = h0[b * HH + 2 * p + 1];
    g_h[b * HH + 2 * p]     = v0;
    g_h[b * HH + 2 * p + 1] = v1;
    float m = 1.0f - (float)dones[b * TT + 0];
    unsigned h, l; pack2(v0 * m, v1 * m, h, l);
    g_hhi[0][i] = h; g_hlo[0][i] = l;
}

__global__ void copy_hlast_kernel(float* __restrict__ dst)
{
    int i = blockIdx.x * 256 + threadIdx.x;
    if (i < BB * HH) dst[i] = g_h[i];
}

// ---------------------------------------------------------------------------
// gi GEMM (unchanged from R2): g_gi = x @ W_ih^T + b_ih, bf16 hi/lo 3 passes
// ---------------------------------------------------------------------------
__global__ __launch_bounds__(512) void gi_gemm_kernel(const float* __restrict__ bias)
{
    __shared__ unsigned sAh[128][20], sAl[128][20], sBh[128][20], sBl[128][20];

    const int tid  = threadIdx.x;
    const int lane = tid & 31;
    const int wid  = tid >> 5;
    const int n0   = blockIdx.x * 128;
    const int m0   = blockIdx.y * 128;
    const int mw   = (wid & 3) * 32;
    const int nw   = (wid >> 2) * 32;
    const int g    = lane >> 2;
    const int t4   = lane & 3;

    float Da[8][4], Db[8][4];
#pragma unroll
    for (int i = 0; i < 8; ++i)
#pragma unroll
        for (int j = 0; j < 4; ++j) { Da[i][j] = 0.f; Db[i][j] = 0.f; }

    const int lrow = tid >> 2;
    const int lq   = (tid & 3) * 4;

    for (int c = 0; c < 32; ++c) {
        size_t abase = (size_t)(m0 + lrow) * KP + c * 16 + lq;
        size_t bbase = (size_t)(n0 + lrow) * KP + c * 16 + lq;
        *(uint4*)&sAh[lrow][lq] = *(const uint4*)&g_xhi[abase];
        *(uint4*)&sAl[lrow][lq] = *(const uint4*)&g_xlo[abase];
        *(uint4*)&sBh[lrow][lq] = *(const uint4*)&g_wihhi[bbase];
        *(uint4*)&sBl[lrow][lq] = *(const uint4*)&g_wihlo[bbase];
        __syncthreads();

#pragma unroll
        for (int kt = 0; kt < 2; ++kt) {
            const int o = kt * 8;
            unsigned ahi[2][4], alo[2][4], bhi[4][2];
#pragma unroll
            for (int mt = 0; mt < 2; ++mt) {
                int r = mw + mt * 16 + g;
                ahi[mt][0] = sAh[r][o + t4];     ahi[mt][1] = sAh[r + 8][o + t4];
                ahi[mt][2] = sAh[r][o + 4 + t4]; ahi[mt][3] = sAh[r + 8][o + 4 + t4];
                alo[mt][0] = sAl[r][o + t4];     alo[mt][1] = sAl[r + 8][o + t4];
                alo[mt][2] = sAl[r][o + 4 + t4]; alo[mt][3] = sAl[r + 8][o + 4 + t4];
            }
#pragma unroll
            for (int nt = 0; nt < 4; ++nt) {
                int rn = nw + nt * 8 + g;
                bhi[nt][0] = sBh[rn][o + t4];
                bhi[nt][1] = sBh[rn][o + 4 + t4];
            }
#pragma unroll
            for (int nt = 0; nt < 4; ++nt)
#pragma unroll
                for (int mt = 0; mt < 2; ++mt)
                    mma_bf16(Da[nt * 2 + mt], ahi[mt][0], ahi[mt][1], ahi[mt][2], ahi[mt][3],
                             bhi[nt][0], bhi[nt][1]);
#pragma unroll
            for (int nt = 0; nt < 4; ++nt)
#pragma unroll
                for (int mt = 0; mt < 2; ++mt)
                    mma_bf16(Db[nt * 2 + mt], alo[mt][0], alo[mt][1], alo[mt][2], alo[mt][3],
                             bhi[nt][0], bhi[nt][1]);
#pragma unroll
            for (int nt = 0; nt < 4; ++nt) {
                int rn = nw + nt * 8 + g;
                unsigned bl0 = sBl[rn][o + t4];
                unsigned bl1 = sBl[rn][o + 4 + t4];
#pragma unroll
                for (int mt = 0; mt < 2; ++mt)
                    mma_bf16(Db[nt * 2 + mt], ahi[mt][0], ahi[mt][1], ahi[mt][2], ahi[mt][3],
                             bl0, bl1);
            }
        }
        __syncthreads();
    }

#pragma unroll
    for (int nt = 0; nt < 4; ++nt) {
        int col = n0 + nw + nt * 8 + 2 * t4;
        float bs0 = bias[col], bs1 = bias[col + 1];
#pragma unroll
        for (int mt = 0; mt < 2; ++mt) {
            int idx = nt * 2 + mt;
            int row = m0 + mw + mt * 16 + g;
            g_gi[(size_t)row * N3H + col]           = Da[idx][0] + Db[idx][0] + bs0;
            g_gi[(size_t)row * N3H + col + 1]       = Da[idx][1] + Db[idx][1] + bs1;
            g_gi[(size_t)(row + 8) * N3H + col]     = Da[idx][2] + Db[idx][2] + bs0;
            g_gi[(size_t)(row + 8) * N3H + col + 1] = Da[idx][3] + Db[idx][3] + bs1;
        }
    }
}

// ---------------------------------------------------------------------------
// Persistent GRU scan: 128 blocks x 256 threads, all 512 steps in one launch.
// Block jb handles j columns [jb*8, jb*8+8) for all 3 gates, all 64 batches.
// W_hh slice (24 rows x 1024 K, hi+lo) resident in SMEM for the whole kernel.
// Warp wid owns K range [wid*128, wid*128+128); K-reduction through SMEM.
// ---------------------------------------------------------------------------
#define SW_STRIDE 516
#define SA_STRIDE 20
#define SWI(arr,row,col) sW[(arr) * (24 * SW_STRIDE) + (row) * SW_STRIDE + (col)]
#define SAI(arr,row,col) sU[widbase + (arr) * 1280 + (row) * SA_STRIDE + (col)]

__global__ __launch_bounds__(256, 1) void gru_scan_kernel(
    const int*   __restrict__ dones,
    const float* __restrict__ bhh,
    float*       __restrict__ out)
{
    extern __shared__ unsigned smem[];
    unsigned* sW = smem;                          // 2*24*516 = 24768 u32
    unsigned* sU = smem + 2 * 24 * SW_STRIDE;     // union: A staging / reduction
    float*    red = (float*)sU;                   // 8*48*32 floats

    const int tid  = threadIdx.x;
    const int lane = tid & 31;
    const int wid  = tid >> 5;
    const int g    = lane >> 2;
    const int t4   = lane & 3;
    const int j0   = blockIdx.x * 8;
    const int widbase = wid * 2560;
    const int kbase   = wid * 64;                 // u32 col offset of this warp's K range

    // ---- load W_hh slice into SMEM (once) ----
#pragma unroll
    for (int q = 0; q < 24; ++q) {
        int id  = q * 256 + tid;                  // 0..6143 uint4
        int arr = (id >= 3072);
        int rem = id - arr * 3072;
        int rr  = rem >> 7;                       // 0..23 (gate*8 + jj)
        int c4  = (rem & 127) << 2;               // u32 col
        const unsigned* src = arr ? g_whhlo : g_whhhi;
        uint4 v = *(const uint4*)&src[(size_t)((rr >> 3) * HH + j0 + (rr & 7)) * KP + c4];
        *(uint4*)&SWI(arr, rr, c4) = v;
    }

    // ---- per-lane epilogue constants ----
    const int je = j0 + 2 * t4;                   // even j column
    const float br0 = bhh[je],          br1 = bhh[je + 1];
    const float bz0 = bhh[HH + je],     bz1 = bhh[HH + je + 1];
    const float bn0 = bhh[2 * HH + je], bn1 = bhh[2 * HH + je + 1];
    const int eb = (wid >> 1) * 16 + (wid & 1) * 8 + g;   // epilogue batch
    __syncthreads();

    for (int t = 0; t < TT; ++t) {
        const int par = t & 1;
        const unsigned* __restrict__ hhi = g_hhi[par];
        const unsigned* __restrict__ hlo = g_hlo[par];

        float D[4][3][4];
#pragma unroll
        for (int mt = 0; mt < 4; ++mt)
#pragma unroll
            for (int nt = 0; nt < 3; ++nt)
#pragma unroll
                for (int c = 0; c < 4; ++c) D[mt][nt][c] = 0.f;

        // prefetch chunk 0: 16 uint4/lane covering [2 arr][64 rows][16 u32]
        uint4 pf[16];
#pragma unroll
        for (int q = 0; q < 16; ++q) {
            int u    = q * 32 + lane;
            int arr  = u >> 8;
            int rem  = u & 255;
            int row  = rem >> 2;
            int quad = rem & 3;
            const unsigned* src = arr ? hlo : hhi;
            pf[q] = *(const uint4*)&src[(size_t)row * KP + kbase + quad * 4];
        }

#pragma unroll
        for (int ch = 0; ch < 4; ++ch) {
            __syncwarp();
#pragma unroll
            for (int q = 0; q < 16; ++q) {
                int u    = q * 32 + lane;
                int arr  = u >> 8;
                int rem  = u & 255;
                int row  = rem >> 2;
                int quad = rem & 3;
                *(uint4*)&SAI(arr, row, quad * 4) = pf[q];
            }
            __syncwarp();
            if (ch < 3) {
#pragma unroll
                for (int q = 0; q < 16; ++q) {
                    int u    = q * 32 + lane;
                    int arr  = u >> 8;
                    int rem  = u & 255;
                    int row  = rem >> 2;
                    int quad = rem & 3;
                    const unsigned* src = arr ? hlo : hhi;
                    pf[q] = *(const uint4*)&src[(size_t)row * KP + kbase + (ch + 1) * 16 + quad * 4];
                }
            }
#pragma unroll
            for (int k2 = 0; k2 < 2; ++k2) {
                const int o = k2 * 8;
                unsigned a[4][8];
#pragma unroll
                for (int mt = 0; mt < 4; ++mt) {
                    int r0 = mt * 16 + g;
                    a[mt][0] = SAI(0, r0,     o + t4);
                    a[mt][1] = SAI(0, r0 + 8, o + t4);
                    a[mt][2] = SAI(0, r0,     o + 4 + t4);
                    a[mt][3] = SAI(0, r0 + 8, o + 4 + t4);
                    a[mt][4] = SAI(1, r0,     o + t4);
                    a[mt][5] = SAI(1, r0 + 8, o + t4);
                    a[mt][6] = SAI(1, r0,     o + 4 + t4);
                    a[mt][7] = SAI(1, r0 + 8, o + 4 + t4);
                }
                const int kcol = kbase + ch * 16 + o;
#pragma unroll
                for (int nt = 0; nt < 3; ++nt) {
                    int rr = nt * 8 + g;
                    unsigned bh0 = SWI(0, rr, kcol + t4);
                    unsigned bh1 = SWI(0, rr, kcol + 4 + t4);
                    unsigned bl0 = SWI(1, rr, kcol + t4);
                    unsigned bl1 = SWI(1, rr, kcol + 4 + t4);
#pragma unroll
                    for (int mt = 0; mt < 4; ++mt) {
                        mma_bf16(D[mt][nt], a[mt][0], a[mt][1], a[mt][2], a[mt][3], bh0, bh1);
                        mma_bf16(D[mt][nt], a[mt][0], a[mt][1], a[mt][2], a[mt][3], bl0, bl1);
                        mma_bf16(D[mt][nt], a[mt][4], a[mt][5], a[mt][6], a[mt][7], bh0, bh1);
                    }
                }
            }
        }

        // ---- K reduction across 8 warps (red aliases A staging) ----
        __syncthreads();
#pragma unroll
        for (int mt = 0; mt < 4; ++mt)
#pragma unroll
            for (int nt = 0; nt < 3; ++nt)
#pragma unroll
                for (int c = 0; c < 4; ++c) {
                    int e = (mt * 4 + c) * 3 + nt;
                    red[(wid * 48 + e) * 32 + lane] = D[mt][nt][c];
                }
        __syncthreads();

        float s[6];
#pragma unroll
        for (int k = 0; k < 6; ++k) {
            int e = wid * 6 + k;
            float acc = 0.f;
#pragma unroll
            for (int w2 = 0; w2 < 8; ++w2)
                acc += red[(w2 * 48 + e) * 32 + lane];
            s[k] = acc;
        }

        // ---- fused gate epilogue: one (b, j-pair) per lane ----
        {
            const float m  = 1.0f - (float)dones[eb * TT + t];
            float2 hp = *(const float2*)&g_h[eb * HH + je];
            const float h0v = hp.x * m, h1v = hp.y * m;

            const float* gip = g_gi + ((size_t)eb * TT + t) * N3H;
            float2 gr = *(const float2*)&gip[je];
            float2 gz = *(const float2*)&gip[HH + je];
            float2 gn = *(const float2*)&gip[2 * HH + je];

            float r0 = sigf(gr.x + s[0] + br0);
            float r1 = sigf(gr.y + s[3] + br1);
            float z0 = sigf(gz.x + s[1] + bz0);
            float z1 = sigf(gz.y + s[4] + bz1);
            float n0 = tanhf(gn.x + r0 * (s[2] + bn0));
            float n1 = tanhf(gn.y + r1 * (s[5] + bn1));
            float hn0 = (1.f - z0) * n0 + z0 * h0v;
            float hn1 = (1.f - z1) * n1 + z1 * h1v;

            float2 o2; o2.x = hn0; o2.y = hn1;
            *(float2*)&out[((size_t)eb * TT + t) * HH + je] = o2;
            *(float2*)&g_h[eb * HH + je] = o2;

            float nm = (t + 1 < TT) ? (1.0f - (float)dones[eb * TT + t + 1]) : 1.0f;
            unsigned ph, pl;
            pack2(hn0 * nm, hn1 * nm, ph, pl);
            g_hhi[par ^ 1][eb * KP + (j0 >> 1) + t4] = ph;
            g_hlo[par ^ 1][eb * KP + (j0 >> 1) + t4] = pl;
        }

        // ---- software grid barrier ----
        __syncthreads();
        if (t + 1 < TT) {
            if (tid == 0) {
                asm volatile("red.release.gpu.add.u32 [%0], %1;"
                             :: "l"(&g_bar), "r"(1u) : "memory");
                const unsigned target = 128u * (unsigned)(t + 1);
                while (ld_acquire_u32(&g_bar) < target) { }
            }
            __syncthreads();
        }
    }
}

// ---------------------------------------------------------------------------
// launch
// ---------------------------------------------------------------------------
extern "C" void kernel_launch(void* const* d_in, const int* in_sizes, int n_in,
                              void* d_out, int out_size)
{
    const float* x     = (const float*)d_in[0];
    const float* h0    = (const float*)d_in[1];
    const int*   dones = (const int*)  d_in[2];
    const float* Wih   = (const float*)d_in[3];
    const float* Whh   = (const float*)d_in[4];
    const float* bih   = (const float*)d_in[5];
    const float* bhh   = (const float*)d_in[6];

    float* out   = (float*)d_out;
    float* hlast = out + (size_t)BB * TT * HH;

    const int SCAN_SMEM = (2 * 24 * SW_STRIDE + 8 * 2560) * 4;   // 180992 B
    cudaFuncSetAttribute(gru_scan_kernel, cudaFuncAttributeMaxDynamicSharedMemorySize, SCAN_SMEM);

    pack_x_kernel<<<(MM * KP + 255) / 256, 256>>>(x);
    pack_w_kernel<<<(N3H * KP + 255) / 256, 256>>>(Wih, 0);
    pack_w_kernel<<<(N3H * KP + 255) / 256, 256>>>(Whh, 1);
    init_h_kernel<<<(BB * KP + 255) / 256, 256>>>(h0, dones);

    {
        dim3 grid(N3H / 128, MM / 128);
        gi_gemm_kernel<<<grid, 512>>>(bih);
    }

    gru_scan_kernel<<<128, 256, SCAN_SMEM>>>(dones, bhh, out);

    copy_hlast_kernel<<<(BB * HH + 255) / 256, 256>>>(hlast);
}